// round 10
// baseline (speedup 1.0000x reference)
#include <cuda_runtime.h>

// Problem constants
#define NN 4
#define CC 256
#define HW 20480            // 128*160
#define PP (NN*HW)          // 81920 pixels
#define NB 64               // depth bins
#define CHUNK 10240         // pixels per block chunk
#define NCHUNKS (PP/CHUNK)  // 8
#define K1_BLOCKS 80

// Scratch (no device allocation allowed -> __device__ globals)
__device__ unsigned char g_idx[PP];
__device__ int   g_hist[K1_BLOCKS*NB];   // per-k1-block histogram partials
__device__ float g_invcnt[NB];
__device__ float g_sums[2*NB*CC];        // [tensor][bin][channel]

// ---------------------------------------------------------------------------
// K1: bin index per pixel (uint8) + per-block histogram partials
//     + zero g_sums and out (consumed only by later kernels).
__device__ __forceinline__ unsigned char bin_of(float d) {
    float t = d * 64.0f;                       // bin_size = 1/64 exactly
    if (t >= 0.0f && t < 64.0f) return (unsigned char)(int)t;  // trunc == ref
    return (unsigned char)64;                  // overflow/invalid bin
}

__global__ void __launch_bounds__(256) k1_idx(const float* __restrict__ depth,
                                              float* __restrict__ out) {
    __shared__ int hist[NB];
    const int tid = threadIdx.x;
    if (tid < NB) hist[tid] = 0;
    __syncthreads();

    const int g = blockIdx.x * 256 + tid;      // 80*256 = 20480 float4s
    float4 d = ((const float4*)depth)[g];
    uchar4 b4;
    b4.x = bin_of(d.x); b4.y = bin_of(d.y); b4.z = bin_of(d.z); b4.w = bin_of(d.w);
    ((uchar4*)g_idx)[g] = b4;
    if (b4.x < 64) atomicAdd(&hist[b4.x], 1);
    if (b4.y < 64) atomicAdd(&hist[b4.y], 1);
    if (b4.z < 64) atomicAdd(&hist[b4.z], 1);
    if (b4.w < 64) atomicAdd(&hist[b4.w], 1);

    // zero scratch consumed by later kernels
    for (int i = g; i < 2*NB*CC; i += K1_BLOCKS*256) g_sums[i] = 0.f;
    if (g == 0) out[0] = 0.f;

    __syncthreads();
    if (tid < NB) g_hist[blockIdx.x*NB + tid] = hist[tid];
}

// ---------------------------------------------------------------------------
// KC: reduce per-block histogram partials -> 1/max(count,1).
// (also occupies stream index 1 so k2(T) lands at the sampled index 3)
__global__ void __launch_bounds__(256) kc_counts() {
    __shared__ float part[4][NB];
    const int tid = threadIdx.x;
    const int bin = tid & 63, grp = tid >> 6;  // 4 groups x 20 rows
    int cnt = 0;
    #pragma unroll 5
    for (int p = grp*20; p < grp*20 + 20; ++p) cnt += g_hist[p*NB + bin];
    part[grp][bin] = (float)cnt;
    __syncthreads();
    if (tid < NB) {
        float c = part[0][tid] + part[1][tid] + part[2][tid] + part[3][tid];
        g_invcnt[tid] = 1.0f / fmaxf(c, 1.0f);
    }
}

// ---------------------------------------------------------------------------
// K2: streaming segment-sum (one tensor per launch).
// Block = 128 threads = 4 warps = 4 channels; warp lanes stream pixels.
// grid = (chunk 0..7, cgroup 0..63) -> 512 blocks, 32KB smem, 7 blocks/SM.
// Private smem accumulator column per thread: acc[bin][tid] (bank = tid%32,
// conflict-free, race-free RMW, no atomics in the hot loop).
__global__ void __launch_bounds__(128) k2_accum(const float* __restrict__ F,
                                                float* __restrict__ sums) {
    extern __shared__ float acc[];             // [NB][128] = 32 KB
    const int tid  = threadIdx.x;
    const int warp = tid >> 5;
    const int lane = tid & 31;
    const int chunk = blockIdx.x;              // 0..7
    const int n   = chunk >> 1;
    const int hw0 = (chunk & 1) * CHUNK;
    const int c   = blockIdx.y * 4 + warp;     // this warp's channel

    const unsigned char* __restrict__ ib = g_idx + n*HW + hw0;
    const float* __restrict__ src = F + ((long)(n*CC + c))*HW + hw0;

    for (int i = tid; i < NB*128; i += 128) acc[i] = 0.f;
    __syncthreads();

    #pragma unroll 2
    for (int it = 0; it < CHUNK/256; ++it) {   // 40 iters, 8 px/lane/iter
        const int p = it*256 + lane*4;
        float4 v0 = *(const float4*)(src + p);
        float4 v1 = *(const float4*)(src + p + 128);
        uchar4 b0 = *(const uchar4*)(ib + p);
        uchar4 b1 = *(const uchar4*)(ib + p + 128);
        if (b0.x < 64) acc[(int)b0.x*128 + tid] += v0.x;
        if (b0.y < 64) acc[(int)b0.y*128 + tid] += v0.y;
        if (b0.z < 64) acc[(int)b0.z*128 + tid] += v0.z;
        if (b0.w < 64) acc[(int)b0.w*128 + tid] += v0.w;
        if (b1.x < 64) acc[(int)b1.x*128 + tid] += v1.x;
        if (b1.y < 64) acc[(int)b1.y*128 + tid] += v1.y;
        if (b1.z < 64) acc[(int)b1.z*128 + tid] += v1.z;
        if (b1.w < 64) acc[(int)b1.w*128 + tid] += v1.w;
    }
    __syncthreads();

    // Tail reduce: lane l sums bins l and l+32 across this warp's 32 columns.
    // Rotation (j+lane)&31 keeps all lanes on distinct banks every step.
    const float* aw = acc + warp*32;
    float s0 = 0.f, s1 = 0.f;
    #pragma unroll
    for (int j = 0; j < 32; ++j) {
        const int col = (j + lane) & 31;
        s0 += aw[lane*128 + col];
        s1 += aw[(lane + 32)*128 + col];
    }
    atomicAdd(sums + lane*CC + c,        s0);
    atomicAdd(sums + (lane + 32)*CC + c, s1);
}

// ---------------------------------------------------------------------------
// K3 (fused protos + loss): 64 blocks x 256 threads, 128KB smem.
// Normalization: 2 threads per row, 32 INDEPENDENT LDG.128 per pass (deep MLP,
// no serial warp-per-row chains). Gram row i with register-cached pSi/pTi.
__global__ void __launch_bounds__(256) k3_loss(float* __restrict__ out) {
    extern __shared__ float prot[];            // [2*NB][CC] = 128 KB
    const int tid = threadIdx.x, warp = tid >> 5, lane = tid & 31;

    // --- normalize all 128 (tensor,bin) rows ---
    {
        const int r = tid >> 1;                // 0..127
        const int h = tid & 1;                 // which 128-channel half
        const float ic = g_invcnt[r & 63];
        const float4* __restrict__ src = (const float4*)(g_sums + r*CC + h*128);

        // pass 1: sum of squares (32 independent loads)
        float ss = 0.f;
        #pragma unroll
        for (int k = 0; k < 32; ++k) {
            float4 m = src[k];
            m.x *= ic; m.y *= ic; m.z *= ic; m.w *= ic;
            ss += m.x*m.x + m.y*m.y + m.z*m.z + m.w*m.w;
        }
        ss += __shfl_xor_sync(0xffffffffu, ss, 1);   // partner = other half
        const float inv = ic / fmaxf(sqrtf(ss), 1e-12f);

        // pass 2: scale + store to smem (L2-hit reloads, independent)
        float4* __restrict__ dst = (float4*)(prot + r*CC + h*128);
        #pragma unroll
        for (int k = 0; k < 32; ++k) {
            float4 m = src[k];
            m.x *= inv; m.y *= inv; m.z *= inv; m.w *= inv;
            dst[k] = m;
        }
    }
    __syncthreads();

    // --- Gram row i: sum_j (pSi.pSj - pTi.pTj)^2 ---
    const int i = blockIdx.x;
    float pS[8], pT[8];
    #pragma unroll
    for (int k = 0; k < 8; ++k) {
        pS[k] = prot[i*CC + lane + 32*k];
        pT[k] = prot[(NB + i)*CC + lane + 32*k];
    }
    float accv = 0.f;
    for (int j = warp; j < NB; j += 8) {
        const float* __restrict__ qS = prot + j*CC;
        const float* __restrict__ qT = prot + (NB + j)*CC;
        float sS = 0.f, sT = 0.f;
        #pragma unroll
        for (int k = 0; k < 8; ++k) {
            sS += pS[k] * qS[lane + 32*k];
            sT += pT[k] * qT[lane + 32*k];
        }
        #pragma unroll
        for (int o = 16; o; o >>= 1) {
            sS += __shfl_xor_sync(0xffffffffu, sS, o);
            sT += __shfl_xor_sync(0xffffffffu, sT, o);
        }
        if (lane == 0) { const float d = sS - sT; accv += d*d; }
    }
    if (lane == 0) atomicAdd(out, accv * (1.0f/(NB*NB)));
}

// ---------------------------------------------------------------------------
extern "C" void kernel_launch(void* const* d_in, const int* in_sizes, int n_in,
                              void* d_out, int out_size) {
    (void)in_sizes; (void)n_in; (void)out_size;
    const float* S     = (const float*)d_in[0];
    const float* T     = (const float*)d_in[1];
    const float* depth = (const float*)d_in[2];
    float* out = (float*)d_out;

    cudaFuncSetAttribute(k3_loss, cudaFuncAttributeMaxDynamicSharedMemorySize,
                         2*NB*CC*(int)sizeof(float));

    float* sums = nullptr;
    cudaGetSymbolAddress((void**)&sums, g_sums);

    // stream index:      0        1         2          3          4
    k1_idx  <<<K1_BLOCKS, 256>>>(depth, out);
    kc_counts<<<1, 256>>>();
    k2_accum<<<dim3(NCHUNKS, CC/4), 128, NB*128*sizeof(float)>>>(S, sums);
    k2_accum<<<dim3(NCHUNKS, CC/4), 128, NB*128*sizeof(float)>>>(T, sums + NB*CC);
    k3_loss <<<NB, 256, 2*NB*CC*sizeof(float)>>>(out);
}

// round 11
// speedup vs baseline: 1.2733x; 1.2733x over previous
#include <cuda_runtime.h>

// Problem constants
#define NN 4
#define CC 256
#define HW 20480            // 128*160
#define PP (NN*HW)          // 81920 pixels
#define NB 64               // depth bins
#define CHUNK 10240         // pixels per block chunk
#define NCHUNKS (PP/CHUNK)  // 8
#define K1_BLOCKS 80

// Scratch (no device allocation allowed -> __device__ globals)
__device__ unsigned char g_idx[PP];
__device__ int   g_hist[K1_BLOCKS*NB];   // per-k1-block histogram partials
__device__ float g_sums[2*NB*CC];        // [tensor][bin][channel]

// ---------------------------------------------------------------------------
// K1: bin index per pixel (uint8) + per-block histogram partials
//     + zero g_sums and out (consumed only by later kernels).
__device__ __forceinline__ unsigned char bin_of(float d) {
    float t = d * 64.0f;                       // bin_size = 1/64 exactly
    if (t >= 0.0f && t < 64.0f) return (unsigned char)(int)t;  // trunc == ref
    return (unsigned char)64;                  // overflow/invalid bin
}

__global__ void __launch_bounds__(256) k1_idx(const float* __restrict__ depth,
                                              float* __restrict__ out) {
    __shared__ int hist[NB];
    const int tid = threadIdx.x;
    if (tid < NB) hist[tid] = 0;
    __syncthreads();

    const int g = blockIdx.x * 256 + tid;      // 80*256 = 20480 float4s
    float4 d = ((const float4*)depth)[g];
    uchar4 b4;
    b4.x = bin_of(d.x); b4.y = bin_of(d.y); b4.z = bin_of(d.z); b4.w = bin_of(d.w);
    ((uchar4*)g_idx)[g] = b4;
    if (b4.x < 64) atomicAdd(&hist[b4.x], 1);
    if (b4.y < 64) atomicAdd(&hist[b4.y], 1);
    if (b4.z < 64) atomicAdd(&hist[b4.z], 1);
    if (b4.w < 64) atomicAdd(&hist[b4.w], 1);

    // zero scratch consumed by later kernels
    for (int i = g; i < 2*NB*CC; i += K1_BLOCKS*256) g_sums[i] = 0.f;
    if (g == 0) out[0] = 0.f;

    __syncthreads();
    if (tid < NB) g_hist[blockIdx.x*NB + tid] = hist[tid];
}

// ---------------------------------------------------------------------------
// K2: streaming segment-sum, both tensors in one grid.
// Block = 128 threads = 4 warps = 4 channels; warp lanes stream pixels.
// grid = (chunk 0..7, cgroup 0..63, tensor 0..1) -> 1024 blocks, 32KB smem,
// 7 blocks/SM (capacity 1036) -> one full wave at 43% occ.
// 2-stage software pipeline: next iter's loads in flight during the 16 smem
// RMWs of the current iter. Private smem column per thread: acc[bin][tid]
// (bank = tid%32 -> conflict-free, race-free, no atomics in the hot loop).
__global__ void __launch_bounds__(128) k2_accum(const float* __restrict__ S,
                                                const float* __restrict__ T) {
    extern __shared__ float acc[];             // [NB][128] = 32 KB
    const int tid  = threadIdx.x;
    const int warp = tid >> 5;
    const int lane = tid & 31;
    const int chunk = blockIdx.x;              // 0..7
    const int n   = chunk >> 1;
    const int hw0 = (chunk & 1) * CHUNK;
    const int c   = blockIdx.y * 4 + warp;     // this warp's channel

    const uchar4* __restrict__ ib4 =
        (const uchar4*)(g_idx + n*HW + hw0);
    const float4* __restrict__ src4 = (const float4*)(
        (blockIdx.z ? T : S) + ((long)(n*CC + c))*HW + hw0);

    for (int i = tid; i < NB*128; i += 128) acc[i] = 0.f;
    __syncthreads();

    // prologue: iter 0 loads
    float4 v0 = __ldcs((const float4*)&src4[lane]);
    float4 v1 = __ldcs((const float4*)&src4[lane + 32]);
    uchar4 b0 = ib4[lane];
    uchar4 b1 = ib4[lane + 32];

    #pragma unroll 1
    for (int it = 0; it < CHUNK/256; ++it) {   // 40 iters, 8 px/lane/iter
        float4 nv0, nv1; uchar4 nb0, nb1;
        if (it + 1 < CHUNK/256) {              // prefetch next iter
            const int q = (it + 1)*64 + lane;
            nv0 = __ldcs(&src4[q]);
            nv1 = __ldcs(&src4[q + 32]);
            nb0 = ib4[q];
            nb1 = ib4[q + 32];
        }
        if (b0.x < 64) acc[(int)b0.x*128 + tid] += v0.x;
        if (b0.y < 64) acc[(int)b0.y*128 + tid] += v0.y;
        if (b0.z < 64) acc[(int)b0.z*128 + tid] += v0.z;
        if (b0.w < 64) acc[(int)b0.w*128 + tid] += v0.w;
        if (b1.x < 64) acc[(int)b1.x*128 + tid] += v1.x;
        if (b1.y < 64) acc[(int)b1.y*128 + tid] += v1.y;
        if (b1.z < 64) acc[(int)b1.z*128 + tid] += v1.z;
        if (b1.w < 64) acc[(int)b1.w*128 + tid] += v1.w;
        v0 = nv0; v1 = nv1; b0 = nb0; b1 = nb1;
    }
    __syncthreads();

    // Tail reduce: lane l sums bins l and l+32 across this warp's 32 columns.
    // Rotation (j+lane)&31 keeps all lanes on distinct banks every step.
    const float* aw = acc + warp*32;
    float s0 = 0.f, s1 = 0.f;
    #pragma unroll
    for (int j = 0; j < 32; ++j) {
        const int col = (j + lane) & 31;
        s0 += aw[lane*128 + col];
        s1 += aw[(lane + 32)*128 + col];
    }
    float* dst = g_sums + blockIdx.z*NB*CC + c;
    atomicAdd(dst + lane*CC,        s0);
    atomicAdd(dst + (lane + 32)*CC, s1);
}

// ---------------------------------------------------------------------------
// K3 (fused counts + protos + loss): 64 blocks x 256 threads, 128KB smem.
// Counts: 20 fully-unrolled INDEPENDENT L2 loads per thread + smem combine.
// Normalization: 2 threads per row, 32 independent LDG.128 per pass.
// Gram row i with register-cached pSi/pTi.
__global__ void __launch_bounds__(256) k3_loss(float* __restrict__ out) {
    extern __shared__ float prot[];            // [2*NB][CC] = 128 KB
    __shared__ int   cpart[256];
    __shared__ float inv_cnt[NB];
    const int tid = threadIdx.x, warp = tid >> 5, lane = tid & 31;

    // --- counts: 64 bins x 4 groups of 20 partial rows ---
    {
        const int bin = tid & 63, grp = tid >> 6;
        int cnt = 0;
        #pragma unroll
        for (int p = 0; p < 20; ++p) cnt += g_hist[(grp*20 + p)*NB + bin];
        cpart[tid] = cnt;
    }
    __syncthreads();
    if (tid < NB) {
        float c = (float)(cpart[tid] + cpart[tid+64] + cpart[tid+128] + cpart[tid+192]);
        inv_cnt[tid] = 1.0f / fmaxf(c, 1.0f);
    }
    __syncthreads();

    // --- normalize all 128 (tensor,bin) rows ---
    {
        const int r = tid >> 1;                // 0..127
        const int h = tid & 1;                 // which 128-channel half
        const float ic = inv_cnt[r & 63];
        const float4* __restrict__ src = (const float4*)(g_sums + r*CC + h*128);

        // pass 1: sum of squares (32 independent loads)
        float ss = 0.f;
        #pragma unroll
        for (int k = 0; k < 32; ++k) {
            float4 m = src[k];
            m.x *= ic; m.y *= ic; m.z *= ic; m.w *= ic;
            ss += m.x*m.x + m.y*m.y + m.z*m.z + m.w*m.w;
        }
        ss += __shfl_xor_sync(0xffffffffu, ss, 1);   // partner = other half
        const float inv = ic / fmaxf(sqrtf(ss), 1e-12f);

        // pass 2: scale + store to smem (L2-hit reloads, independent)
        float4* __restrict__ dst = (float4*)(prot + r*CC + h*128);
        #pragma unroll
        for (int k = 0; k < 32; ++k) {
            float4 m = src[k];
            m.x *= inv; m.y *= inv; m.z *= inv; m.w *= inv;
            dst[k] = m;
        }
    }
    __syncthreads();

    // --- Gram row i: sum_j (pSi.pSj - pTi.pTj)^2 ---
    const int i = blockIdx.x;
    float pS[8], pT[8];
    #pragma unroll
    for (int k = 0; k < 8; ++k) {
        pS[k] = prot[i*CC + lane + 32*k];
        pT[k] = prot[(NB + i)*CC + lane + 32*k];
    }
    float accv = 0.f;
    for (int j = warp; j < NB; j += 8) {
        const float* __restrict__ qS = prot + j*CC;
        const float* __restrict__ qT = prot + (NB + j)*CC;
        float sS = 0.f, sT = 0.f;
        #pragma unroll
        for (int k = 0; k < 8; ++k) {
            sS += pS[k] * qS[lane + 32*k];
            sT += pT[k] * qT[lane + 32*k];
        }
        #pragma unroll
        for (int o = 16; o; o >>= 1) {
            sS += __shfl_xor_sync(0xffffffffu, sS, o);
            sT += __shfl_xor_sync(0xffffffffu, sT, o);
        }
        if (lane == 0) { const float d = sS - sT; accv += d*d; }
    }
    if (lane == 0) atomicAdd(out, accv * (1.0f/(NB*NB)));
}

// ---------------------------------------------------------------------------
extern "C" void kernel_launch(void* const* d_in, const int* in_sizes, int n_in,
                              void* d_out, int out_size) {
    (void)in_sizes; (void)n_in; (void)out_size;
    const float* S     = (const float*)d_in[0];
    const float* T     = (const float*)d_in[1];
    const float* depth = (const float*)d_in[2];
    float* out = (float*)d_out;

    cudaFuncSetAttribute(k3_loss, cudaFuncAttributeMaxDynamicSharedMemorySize,
                         2*NB*CC*(int)sizeof(float));

    k1_idx  <<<K1_BLOCKS, 256>>>(depth, out);
    k2_accum<<<dim3(NCHUNKS, CC/4, 2), 128, NB*128*sizeof(float)>>>(S, T);
    k3_loss <<<NB, 256, 2*NB*CC*sizeof(float)>>>(out);
}

// round 15
// speedup vs baseline: 1.3612x; 1.0690x over previous
#include <cuda_runtime.h>

// Problem constants
#define NN 4
#define CC 256
#define HW 20480            // 128*160
#define PP (NN*HW)          // 81920 pixels
#define NB 64               // depth bins
#define CHUNK 10240         // pixels per block chunk
#define NCHUNKS (PP/CHUNK)  // 8
#define K1_BLOCKS 80

// Scratch (no device allocation allowed -> __device__ globals)
__device__ unsigned char g_idx[PP];
__device__ int   g_hist[K1_BLOCKS*NB];   // per-k1-block histogram partials
__device__ float g_sums[2*NB*CC];        // [tensor][bin][channel]

// ---------------------------------------------------------------------------
// K1: bin index per pixel (uint8) + per-block histogram partials
//     + zero g_sums and out (consumed only by later kernels).
__device__ __forceinline__ unsigned char bin_of(float d) {
    float t = d * 64.0f;                       // bin_size = 1/64 exactly
    if (t >= 0.0f && t < 64.0f) return (unsigned char)(int)t;  // trunc == ref
    return (unsigned char)64;                  // overflow/invalid bin
}

__global__ void __launch_bounds__(256) k1_idx(const float* __restrict__ depth,
                                              float* __restrict__ out) {
    __shared__ int hist[NB];
    const int tid = threadIdx.x;
    if (tid < NB) hist[tid] = 0;
    __syncthreads();

    const int g = blockIdx.x * 256 + tid;      // 80*256 = 20480 float4s
    float4 d = ((const float4*)depth)[g];
    uchar4 b4;
    b4.x = bin_of(d.x); b4.y = bin_of(d.y); b4.z = bin_of(d.z); b4.w = bin_of(d.w);
    ((uchar4*)g_idx)[g] = b4;
    if (b4.x < 64) atomicAdd(&hist[b4.x], 1);
    if (b4.y < 64) atomicAdd(&hist[b4.y], 1);
    if (b4.z < 64) atomicAdd(&hist[b4.z], 1);
    if (b4.w < 64) atomicAdd(&hist[b4.w], 1);

    // zero scratch consumed by later kernels
    for (int i = g; i < 2*NB*CC; i += K1_BLOCKS*256) g_sums[i] = 0.f;
    if (g == 0) out[0] = 0.f;

    __syncthreads();
    if (tid < NB) g_hist[blockIdx.x*NB + tid] = hist[tid];
}

// ---------------------------------------------------------------------------
// K2: streaming segment-sum, both tensors in one grid (EXACT R6 body — the
// measured-good ~44us configuration; no __ldcs, no manual pipeline: ptxas
// front-batches the 4 loads of the unroll-2 body on its own).
// Block = 128 threads = 4 warps = 4 channels; warp lanes stream pixels.
// grid = (chunk 0..7, cgroup 0..63, tensor 0..1) -> 1024 blocks, 32KB smem,
// 7 blocks/SM (capacity 1036) -> one full wave at 43% occ.
// Private smem accumulator column per thread: acc[bin][tid] (bank = tid%32,
// conflict-free, race-free RMW, no atomics in the hot loop).
__global__ void __launch_bounds__(128) k2_accum(const float* __restrict__ S,
                                                const float* __restrict__ T) {
    extern __shared__ float acc[];             // [NB][128] = 32 KB
    const int tid  = threadIdx.x;
    const int warp = tid >> 5;
    const int lane = tid & 31;
    const int chunk = blockIdx.x;              // 0..7
    const int n   = chunk >> 1;
    const int hw0 = (chunk & 1) * CHUNK;
    const int c   = blockIdx.y * 4 + warp;     // this warp's channel

    const unsigned char* __restrict__ ib = g_idx + n*HW + hw0;
    const float* __restrict__ src =
        (blockIdx.z ? T : S) + ((long)(n*CC + c))*HW + hw0;

    for (int i = tid; i < NB*128; i += 128) acc[i] = 0.f;
    __syncthreads();

    #pragma unroll 2
    for (int it = 0; it < CHUNK/256; ++it) {   // 40 iters, 8 px/lane/iter
        const int p = it*256 + lane*4;
        float4 v0 = *(const float4*)(src + p);
        float4 v1 = *(const float4*)(src + p + 128);
        uchar4 b0 = *(const uchar4*)(ib + p);
        uchar4 b1 = *(const uchar4*)(ib + p + 128);
        if (b0.x < 64) acc[(int)b0.x*128 + tid] += v0.x;
        if (b0.y < 64) acc[(int)b0.y*128 + tid] += v0.y;
        if (b0.z < 64) acc[(int)b0.z*128 + tid] += v0.z;
        if (b0.w < 64) acc[(int)b0.w*128 + tid] += v0.w;
        if (b1.x < 64) acc[(int)b1.x*128 + tid] += v1.x;
        if (b1.y < 64) acc[(int)b1.y*128 + tid] += v1.y;
        if (b1.z < 64) acc[(int)b1.z*128 + tid] += v1.z;
        if (b1.w < 64) acc[(int)b1.w*128 + tid] += v1.w;
    }
    __syncthreads();

    // Tail reduce: lane l sums bins l and l+32 across this warp's 32 columns.
    // Rotation (j+lane)&31 keeps all lanes on distinct banks every step.
    const float* aw = acc + warp*32;
    float s0 = 0.f, s1 = 0.f;
    #pragma unroll
    for (int j = 0; j < 32; ++j) {
        const int col = (j + lane) & 31;
        s0 += aw[lane*128 + col];
        s1 += aw[(lane + 32)*128 + col];
    }
    float* dst = g_sums + blockIdx.z*NB*CC + c;
    atomicAdd(dst + lane*CC,        s0);
    atomicAdd(dst + (lane + 32)*CC, s1);
}

// ---------------------------------------------------------------------------
// K3 (fused counts + protos + loss): 64 blocks x 256 threads, 128KB smem.
// Counts: 20 fully-unrolled INDEPENDENT L2 loads per thread + smem combine.
// Normalization: 2 threads per row, 32 independent LDG.128 per pass.
// Gram row i with register-cached pSi/pTi.
__global__ void __launch_bounds__(256) k3_loss(float* __restrict__ out) {
    extern __shared__ float prot[];            // [2*NB][CC] = 128 KB
    __shared__ int   cpart[256];
    __shared__ float inv_cnt[NB];
    const int tid = threadIdx.x, warp = tid >> 5, lane = tid & 31;

    // --- counts: 64 bins x 4 groups of 20 partial rows ---
    {
        const int bin = tid & 63, grp = tid >> 6;
        int cnt = 0;
        #pragma unroll
        for (int p = 0; p < 20; ++p) cnt += g_hist[(grp*20 + p)*NB + bin];
        cpart[tid] = cnt;
    }
    __syncthreads();
    if (tid < NB) {
        float c = (float)(cpart[tid] + cpart[tid+64] + cpart[tid+128] + cpart[tid+192]);
        inv_cnt[tid] = 1.0f / fmaxf(c, 1.0f);
    }
    __syncthreads();

    // --- normalize all 128 (tensor,bin) rows ---
    {
        const int r = tid >> 1;                // 0..127
        const int h = tid & 1;                 // which 128-channel half
        const float ic = inv_cnt[r & 63];
        const float4* __restrict__ src = (const float4*)(g_sums + r*CC + h*128);

        // pass 1: sum of squares (32 independent loads)
        float ss = 0.f;
        #pragma unroll
        for (int k = 0; k < 32; ++k) {
            float4 m = src[k];
            m.x *= ic; m.y *= ic; m.z *= ic; m.w *= ic;
            ss += m.x*m.x + m.y*m.y + m.z*m.z + m.w*m.w;
        }
        ss += __shfl_xor_sync(0xffffffffu, ss, 1);   // partner = other half
        const float inv = ic / fmaxf(sqrtf(ss), 1e-12f);

        // pass 2: scale + store to smem (L2-hit reloads, independent)
        float4* __restrict__ dst = (float4*)(prot + r*CC + h*128);
        #pragma unroll
        for (int k = 0; k < 32; ++k) {
            float4 m = src[k];
            m.x *= inv; m.y *= inv; m.z *= inv; m.w *= inv;
            dst[k] = m;
        }
    }
    __syncthreads();

    // --- Gram row i: sum_j (pSi.pSj - pTi.pTj)^2 ---
    const int i = blockIdx.x;
    float pS[8], pT[8];
    #pragma unroll
    for (int k = 0; k < 8; ++k) {
        pS[k] = prot[i*CC + lane + 32*k];
        pT[k] = prot[(NB + i)*CC + lane + 32*k];
    }
    float accv = 0.f;
    for (int j = warp; j < NB; j += 8) {
        const float* __restrict__ qS = prot + j*CC;
        const float* __restrict__ qT = prot + (NB + j)*CC;
        float sS = 0.f, sT = 0.f;
        #pragma unroll
        for (int k = 0; k < 8; ++k) {
            sS += pS[k] * qS[lane + 32*k];
            sT += pT[k] * qT[lane + 32*k];
        }
        #pragma unroll
        for (int o = 16; o; o >>= 1) {
            sS += __shfl_xor_sync(0xffffffffu, sS, o);
            sT += __shfl_xor_sync(0xffffffffu, sT, o);
        }
        if (lane == 0) { const float d = sS - sT; accv += d*d; }
    }
    if (lane == 0) atomicAdd(out, accv * (1.0f/(NB*NB)));
}

// ---------------------------------------------------------------------------
extern "C" void kernel_launch(void* const* d_in, const int* in_sizes, int n_in,
                              void* d_out, int out_size) {
    (void)in_sizes; (void)n_in; (void)out_size;
    const float* S     = (const float*)d_in[0];
    const float* T     = (const float*)d_in[1];
    const float* depth = (const float*)d_in[2];
    float* out = (float*)d_out;

    cudaFuncSetAttribute(k3_loss, cudaFuncAttributeMaxDynamicSharedMemorySize,
                         2*NB*CC*(int)sizeof(float));

    k1_idx  <<<K1_BLOCKS, 256>>>(depth, out);
    k2_accum<<<dim3(NCHUNKS, CC/4, 2), 128, NB*128*sizeof(float)>>>(S, T);
    k3_loss <<<NB, 256, 2*NB*CC*sizeof(float)>>>(out);
}